// round 16
// baseline (speedup 1.0000x reference)
#include <cuda_runtime.h>
#include <cuda_fp16.h>
#include <cuda_bf16.h>
#include <cstdint>

#define NN   8192
#define EE   262144
#define DD   64
#define SS   128
#define KK   128
#define NEGK 4

// ---- output layout (tuple flattened in order) ----
#define OUT_ADJ 4LL
#define OUT_P1  (4LL + (long long)NN * NN)
#define OUT_N1  (OUT_P1 + NN)
#define OUT_P2  (OUT_N1 + 4LL * NN)
#define OUT_N2  (OUT_P2 + NN)

// ---- device scratch (no allocation allowed) ----
__device__ float g_h1[NN * DD];
__device__ float g_v1[NN * DD];
__device__ float g_h2[NN * DD];
__device__ float g_v2[NN * DD];
__device__ float g_nbr[NN * DD];
__device__ float g_c1[NN * DD];
__device__ float g_c2[NN * DD];
__device__ float g_score[NN];
__device__ __half g_fh[NN * DD];
__device__ int   g_cnt[NN];      // zero-initialized; k_scan re-zeroes after use
__device__ int   g_rptr[NN + 1];
__device__ int   g_cur[NN];
__device__ uint4 g_edge[EE];     // packed (src, w_bits, aw_bits, 0)

__device__ __forceinline__ float* selBuf(int s) {
    switch (s) {
        case 0: return g_h1;
        case 1: return g_v1;
        case 2: return g_h2;
        case 3: return g_v2;
        case 5: return g_c1;
        case 6: return g_c2;
    }
    return nullptr;
}

// 1-MUFU sigmoid: sigmoid(x) = 0.5*tanh(0.5x) + 0.5
__device__ __forceinline__ float fast_sigmoid(float x) {
    float t;
    asm("tanh.approx.f32 %0, %1;" : "=f"(t) : "f"(0.5f * x));
    return fmaf(0.5f, t, 0.5f);
}

__device__ __forceinline__ uint32_t smem_cast(const void* p) {
    uint32_t a;
    asm("{ .reg .u64 t; cvta.to.shared.u64 t, %1; cvt.u32.u64 %0, t; }"
        : "=r"(a) : "l"(p));
    return a;
}

#define LDSM_X4(r0, r1, r2, r3, addr) \
    asm volatile("ldmatrix.sync.aligned.m8n8.x4.shared.b16 {%0,%1,%2,%3}, [%4];" \
                 : "=r"(r0), "=r"(r1), "=r"(r2), "=r"(r3) : "r"(addr))

// ============================================================
// 1. CSR build: histogram (x4) -> scan (self-cleaning) -> scatter
// ============================================================
__global__ void k_hist(const int* __restrict__ edst) {
    int e4 = blockIdx.x * blockDim.x + threadIdx.x;
    int4 d = ((const int4*)edst)[e4];
    atomicAdd(&g_cnt[d.x], 1);
    atomicAdd(&g_cnt[d.y], 1);
    atomicAdd(&g_cnt[d.z], 1);
    atomicAdd(&g_cnt[d.w], 1);
}

__global__ void k_scan(float* __restrict__ out) {
    __shared__ int partial[1024];
    int t = threadIdx.x;
    int base = t * 8;
    int loc[8];
    int s = 0;
#pragma unroll
    for (int i = 0; i < 8; i++) { loc[i] = s; s += g_cnt[base + i]; }
#pragma unroll
    for (int i = 0; i < 8; i++) g_cnt[base + i] = 0;   // re-zero for next call
    partial[t] = s;
    __syncthreads();
    for (int off = 1; off < 1024; off <<= 1) {
        int v = 0;
        if (t >= off) v = partial[t - off];
        __syncthreads();
        if (t >= off) partial[t] += v;
        __syncthreads();
    }
    int excl = (t == 0) ? 0 : partial[t - 1];
#pragma unroll
    for (int i = 0; i < 8; i++) {
        int v = excl + loc[i];
        g_rptr[base + i] = v;
        g_cur[base + i]  = v;
    }
    if (t == 1023) g_rptr[NN] = partial[1023];
    if (t < 4) out[t] = 0.f;                           // zero scalar outputs
}

__global__ void k_scatter(const int* __restrict__ esrc, const int* __restrict__ edst,
                          const float* __restrict__ ew, const float* __restrict__ aw) {
    int e4 = blockIdx.x * blockDim.x + threadIdx.x;
    int4   s = ((const int4*)esrc)[e4];
    int4   d = ((const int4*)edst)[e4];
    float4 w = ((const float4*)ew)[e4];
    float4 a = ((const float4*)aw)[e4];
    int p0 = atomicAdd(&g_cur[d.x], 1);
    int p1 = atomicAdd(&g_cur[d.y], 1);
    int p2 = atomicAdd(&g_cur[d.z], 1);
    int p3 = atomicAdd(&g_cur[d.w], 1);
    g_edge[p0] = make_uint4(s.x, __float_as_uint(w.x), __float_as_uint(a.x), 0);
    g_edge[p1] = make_uint4(s.y, __float_as_uint(w.y), __float_as_uint(a.y), 0);
    g_edge[p2] = make_uint4(s.z, __float_as_uint(w.z), __float_as_uint(a.z), 0);
    g_edge[p3] = make_uint4(s.w, __float_as_uint(w.w), __float_as_uint(a.w), 0);
}

// ============================================================
// 2. dense [N,64]x[64,64] GEMM (simple form, 64 rows/block)
// ============================================================
__global__ void __launch_bounds__(256) k_gemm64(
    const float* __restrict__ Xext, int xsel,
    const float* __restrict__ W, int ysel)
{
    __shared__ float Xs[64][68];
    __shared__ float Ws[64][68];
    const float* X = Xext ? Xext : selBuf(xsel);
    float* Y = selBuf(ysel);
    int tid = threadIdx.x;
    int rowBase = blockIdx.x * 64;

    for (int i = tid; i < 4096; i += 256)
        Ws[i >> 6][i & 63] = W[i];
    for (int i = tid; i < 4096; i += 256) {
        int r = i >> 6, c = i & 63;
        Xs[r][c] = X[(rowBase + r) * 64 + c];
    }
    __syncthreads();

    int rg = tid >> 2;
    int cg = (tid & 3) * 16;
    float acc[16];
#pragma unroll
    for (int i = 0; i < 16; i++) acc[i] = 0.f;

#pragma unroll 16
    for (int k = 0; k < 64; k++) {
        float x = Xs[rg][k];
#pragma unroll
        for (int q = 0; q < 4; q++) {
            float4 w = *(const float4*)&Ws[k][cg + q * 4];
            acc[q * 4 + 0] += x * w.x;
            acc[q * 4 + 1] += x * w.y;
            acc[q * 4 + 2] += x * w.z;
            acc[q * 4 + 3] += x * w.w;
        }
    }
#pragma unroll
    for (int q = 0; q < 4; q++) {
        float4 v;
        v.x = acc[q * 4 + 0]; v.y = acc[q * 4 + 1];
        v.z = acc[q * 4 + 2]; v.w = acc[q * 4 + 3];
        *(float4*)&Y[(rowBase + rg) * 64 + cg + q * 4] = v;
    }
}

// ============================================================
// 2b. fused tail: nv = prelu(v2@Wq+bq); score; fp16; c1 = nv@B1^T; c2 = nv@B2
// ============================================================
__global__ void __launch_bounds__(256) k_nvfuse(
    const float* __restrict__ Wq, const float* __restrict__ bq,
    const float* __restrict__ aq,
    const float* __restrict__ B1, const float* __restrict__ B2,
    const float* __restrict__ Wsc, const float* __restrict__ bsc)
{
    __shared__ float Xs[64][68];
    __shared__ float Wsm[64][68];
    int tid = threadIdx.x;
    int rowBase = blockIdx.x * 64;
    int rg = tid >> 2;
    int cg = (tid & 3) * 16;

    for (int i = tid; i < 4096; i += 256)
        Wsm[i >> 6][i & 63] = Wq[i];
    for (int i = tid; i < 4096; i += 256) {
        int r = i >> 6, c = i & 63;
        Xs[r][c] = g_v2[(rowBase + r) * 64 + c];
    }
    __syncthreads();

    // nv = prelu(v2 @ Wq + bq)
    float nv[16];
#pragma unroll
    for (int i = 0; i < 16; i++) nv[i] = 0.f;
#pragma unroll 16
    for (int k = 0; k < 64; k++) {
        float x = Xs[rg][k];
#pragma unroll
        for (int q = 0; q < 4; q++) {
            float4 w = *(const float4*)&Wsm[k][cg + q * 4];
            nv[q * 4 + 0] += x * w.x;
            nv[q * 4 + 1] += x * w.y;
            nv[q * 4 + 2] += x * w.z;
            nv[q * 4 + 3] += x * w.w;
        }
    }
    float sl = *aq;
#pragma unroll
    for (int q = 0; q < 4; q++) {
        float4 b = *(const float4*)&bq[cg + q * 4];
        float* a = &nv[q * 4];
        a[0] += b.x; a[1] += b.y; a[2] += b.z; a[3] += b.w;
        a[0] = a[0] >= 0.f ? a[0] : sl * a[0];
        a[1] = a[1] >= 0.f ? a[1] : sl * a[1];
        a[2] = a[2] >= 0.f ? a[2] : sl * a[2];
        a[3] = a[3] >= 0.f ? a[3] : sl * a[3];
    }

    // score + fp16 convert
    {
        float p = 0.f;
#pragma unroll
        for (int q = 0; q < 4; q++) {
            float4 w = *(const float4*)&Wsc[cg + q * 4];
            p += nv[q * 4 + 0] * w.x + nv[q * 4 + 1] * w.y
               + nv[q * 4 + 2] * w.z + nv[q * 4 + 3] * w.w;
        }
        p += __shfl_down_sync(0xffffffffu, p, 1, 4);
        p += __shfl_down_sync(0xffffffffu, p, 2, 4);
        __half2* hp = (__half2*)(g_fh + (rowBase + rg) * DD + cg);
#pragma unroll
        for (int q = 0; q < 4; q++) {
            hp[q * 2 + 0] = __floats2half2_rn(nv[q * 4 + 0], nv[q * 4 + 1]);
            hp[q * 2 + 1] = __floats2half2_rn(nv[q * 4 + 2], nv[q * 4 + 3]);
        }
        if ((tid & 3) == 0) g_score[rowBase + rg] = fast_sigmoid(p + bsc[0]);
    }

    // stage nv into Xs; load B1^T into Wsm
    __syncthreads();
#pragma unroll
    for (int j = 0; j < 16; j++) Xs[rg][cg + j] = nv[j];
    for (int i = tid; i < 4096; i += 256)
        Wsm[i >> 6][i & 63] = B1[(i & 63) * 64 + (i >> 6)];   // transpose
    __syncthreads();

    // c1 = nv @ B1^T
    float acc[16];
#pragma unroll
    for (int i = 0; i < 16; i++) acc[i] = 0.f;
#pragma unroll 16
    for (int k = 0; k < 64; k++) {
        float x = Xs[rg][k];
#pragma unroll
        for (int q = 0; q < 4; q++) {
            float4 w = *(const float4*)&Wsm[k][cg + q * 4];
            acc[q * 4 + 0] += x * w.x;
            acc[q * 4 + 1] += x * w.y;
            acc[q * 4 + 2] += x * w.z;
            acc[q * 4 + 3] += x * w.w;
        }
    }
#pragma unroll
    for (int q = 0; q < 4; q++) {
        float4 v;
        v.x = acc[q * 4 + 0]; v.y = acc[q * 4 + 1];
        v.z = acc[q * 4 + 2]; v.w = acc[q * 4 + 3];
        *(float4*)&g_c1[(rowBase + rg) * 64 + cg + q * 4] = v;
    }

    // c2 = nv @ B2
    __syncthreads();
    for (int i = tid; i < 4096; i += 256)
        Wsm[i >> 6][i & 63] = B2[i];
    __syncthreads();
#pragma unroll
    for (int i = 0; i < 16; i++) acc[i] = 0.f;
#pragma unroll 16
    for (int k = 0; k < 64; k++) {
        float x = Xs[rg][k];
#pragma unroll
        for (int q = 0; q < 4; q++) {
            float4 w = *(const float4*)&Wsm[k][cg + q * 4];
            acc[q * 4 + 0] += x * w.x;
            acc[q * 4 + 1] += x * w.y;
            acc[q * 4 + 2] += x * w.z;
            acc[q * 4 + 3] += x * w.w;
        }
    }
#pragma unroll
    for (int q = 0; q < 4; q++) {
        float4 v;
        v.x = acc[q * 4 + 0]; v.y = acc[q * 4 + 1];
        v.z = acc[q * 4 + 2]; v.w = acc[q * 4 + 3];
        *(float4*)&g_c2[(rowBase + rg) * 64 + cg + q * 4] = v;
    }
}

// ============================================================
// 3. CSR aggregation, warp per node, optional fused avg-agg
// ============================================================
__global__ void __launch_bounds__(256) k_agg(
    int hsel, const float* __restrict__ bias, const float* __restrict__ slope,
    int vsel, int fused)
{
    int widx = (blockIdx.x * blockDim.x + threadIdx.x) >> 5;
    int lane = threadIdx.x & 31;
    if (widx >= NN) return;
    const float* h = selBuf(hsel);
    float* v = selBuf(vsel);
    int beg = g_rptr[widx], end = g_rptr[widx + 1];
    float ax = 0.f, ay = 0.f, bx = 0.f, by = 0.f;
#pragma unroll 4
    for (int j = beg; j < end; j++) {
        uint4 e = g_edge[j];
        float w = __uint_as_float(e.y);
        float2 hv = *(const float2*)(h + e.x * DD + lane * 2);
        ax += w * hv.x; ay += w * hv.y;
        if (fused) {
            float w2 = __uint_as_float(e.z);
            bx += w2 * hv.x; by += w2 * hv.y;
        }
    }
    float sl = *slope;
    float2 bb = *(const float2*)(bias + lane * 2);
    float vx = ax + bb.x; vx = vx >= 0.f ? vx : sl * vx;
    float vy = ay + bb.y; vy = vy >= 0.f ? vy : sl * vy;
    *(float2*)(v + widx * DD + lane * 2) = make_float2(vx, vy);
    if (fused)
        *(float2*)(g_nbr + widx * DD + lane * 2) = make_float2(bx, by);
}

// ============================================================
// 5. discriminators (merged: blockIdx.y 0 -> disc1, 1 -> disc2)
// ============================================================
__global__ void k_disc(const float* __restrict__ feat,
                       const int* __restrict__ neg1, const int* __restrict__ neg2,
                       const float* __restrict__ bd1, const float* __restrict__ bd2,
                       float* __restrict__ out) {
    int n = blockIdx.x * blockDim.x + threadIdx.x;
    if (n >= NN) return;
    if (blockIdx.y == 0) {
        float4 c[16];
        const float4* cr = (const float4*)(g_c1 + n * DD);
#pragma unroll
        for (int q = 0; q < 16; q++) c[q] = cr[q];
        float b = bd1[0];
        {
            const float4* f = (const float4*)(feat + n * DD);
            float a = 0.f;
#pragma unroll
            for (int q = 0; q < 16; q++) {
                float4 x = f[q];
                a += x.x * c[q].x + x.y * c[q].y + x.z * c[q].z + x.w * c[q].w;
            }
            out[OUT_P1 + n] = a + b;
        }
#pragma unroll
        for (int k = 0; k < NEGK; k++) {
            int m = neg1[k * NN + n];
            const float4* f = (const float4*)(feat + m * DD);
            float a = 0.f;
#pragma unroll
            for (int q = 0; q < 16; q++) {
                float4 x = f[q];
                a += x.x * c[q].x + x.y * c[q].y + x.z * c[q].z + x.w * c[q].w;
            }
            out[OUT_N1 + (long long)k * NN + n] = a + b;
        }
    } else {
        float4 r[16];
        const float4* nr = (const float4*)(g_nbr + n * DD);
#pragma unroll
        for (int q = 0; q < 16; q++) r[q] = nr[q];
        float b = bd2[0];
        {
            const float4* f = (const float4*)(g_c2 + n * DD);
            float a = 0.f;
#pragma unroll
            for (int q = 0; q < 16; q++) {
                float4 x = f[q];
                a += x.x * r[q].x + x.y * r[q].y + x.z * r[q].z + x.w * r[q].w;
            }
            out[OUT_P2 + n] = a + b;
        }
#pragma unroll
        for (int k = 0; k < NEGK; k++) {
            int m = neg2[k * NN + n];
            const float4* f = (const float4*)(g_c2 + m * DD);
            float a = 0.f;
#pragma unroll
            for (int q = 0; q < 16; q++) {
                float4 x = f[q];
                a += x.x * r[q].x + x.y * r[q].y + x.z * r[q].z + x.w * r[q].w;
            }
            out[OUT_N2 + (long long)k * NN + n] = a + b;
        }
    }
}

// ============================================================
// 6. subgraph losses (no sort needed: max / max-below-mean)
// ============================================================
__device__ __forceinline__ float warpRed(float v) {
#pragma unroll
    for (int o = 16; o; o >>= 1) v += __shfl_xor_sync(0xffffffffu, v, o);
    return v;
}
__device__ __forceinline__ float warpMax(float v) {
#pragma unroll
    for (int o = 16; o; o >>= 1) v = fmaxf(v, __shfl_xor_sync(0xffffffffu, v, o));
    return v;
}

__global__ void k_subg(const int* __restrict__ aidx, const int* __restrict__ nidx,
                       const float* __restrict__ alap, const float* __restrict__ nlap,
                       float* __restrict__ out) {
    int s = blockIdx.x, k = threadIdx.x;
    __shared__ float As[KK], Nss[KK];
    __shared__ float w4[16];
    float sa = g_score[aidx[s * KK + k]];
    float sn = g_score[nidx[s * KK + k]];
    As[k] = sa; Nss[k] = sn;
    __syncthreads();

    const float* la = alap + (size_t)s * KK * KK + k * KK;
    const float* ln = nlap + (size_t)s * KK * KK + k * KK;
    float ta = 0.f, tn = 0.f;
#pragma unroll 8
    for (int j = 0; j < KK; j++) { ta += la[j] * As[j]; tn += ln[j] * Nss[j]; }
    float homk = sa * ta + sn * tn;

    int w = k >> 5, l = k & 31;
    float r0 = warpRed(homk);
    float r1 = warpRed(sa);
    float r2 = warpMax(sa);
    float r3 = warpMax(sn);
    if (l == 0) { w4[0 + w] = r0; w4[4 + w] = r1; w4[8 + w] = r2; w4[12 + w] = r3; }
    __syncthreads();
    float hom_s = w4[0] + w4[1] + w4[2] + w4[3];
    float sum_a = w4[4] + w4[5] + w4[6] + w4[7];
    float max_a = fmaxf(fmaxf(w4[8], w4[9]), fmaxf(w4[10], w4[11]));
    float max_n = fmaxf(fmaxf(w4[12], w4[13]), fmaxf(w4[14], w4[15]));
    float mean = sum_a * (1.f / KK);
    float below = (sa < mean) ? sa : -1e30f;
    float bw = warpMax(below);
    __syncthreads();
    if (l == 0) w4[w] = bw;
    __syncthreads();
    if (k == 0) {
        float bm = fmaxf(fmaxf(w4[0], w4[1]), fmaxf(w4[2], w4[3]));
        float a_at = (bm <= -1e29f) ? max_a : bm;
        atomicAdd(out + 0, fmaxf(0.f, 1.f - max_a + max_n) * (1.f / SS));
        atomicAdd(out + 1, fmaxf(0.f, 1.f - max_a + a_at) * (1.f / SS));
        atomicAdd(out + 2, sum_a * (1.f / SS));
        atomicAdd(out + 3, hom_s * (1.f / (2.f * SS)));
    }
}

// ============================================================
// 7. adj_rebuilt = sigmoid(nv @ nv^T): fp16 HMMA + LDSM loads,
//    upper-triangle tiles, 2 column-halves, staged epilogue.
// ============================================================
__device__ __forceinline__ void mma16816h(float* c, const uint32_t* a, const uint32_t* b) {
    asm volatile(
        "mma.sync.aligned.m16n8k16.row.col.f32.f16.f16.f32 "
        "{%0,%1,%2,%3}, {%4,%5,%6,%7}, {%8,%9}, {%0,%1,%2,%3};\n"
        : "+f"(c[0]), "+f"(c[1]), "+f"(c[2]), "+f"(c[3])
        : "r"(a[0]), "r"(a[1]), "r"(a[2]), "r"(a[3]), "r"(b[0]), "r"(b[1]));
}

#define ADJ_AS   72     // 144B row stride: conflict-free LDSM
#define STG_W    66     // even stride: 8B-aligned float2 accesses
#define ADJ_TILES_SMEM (128 * ADJ_AS * 2 * 2)          // A + B = 36864
#define ADJ_SMEM (ADJ_TILES_SMEM + 128 * STG_W * 4)    // + stage = 70656

__global__ void __launch_bounds__(256, 3) k_adj(float* __restrict__ out) {
    extern __shared__ char dsm[];
    __half* sA = (__half*)dsm;
    __half* sB = (__half*)(dsm + 128 * ADJ_AS * 2);
    float*  stage = (float*)(dsm + ADJ_TILES_SMEM);

    int tid = threadIdx.x;

    // tile id -> (bm, bn) upper triangle, bm <= bn
    int rem = blockIdx.x, bm = 0;
    while (rem >= 64 - bm) { rem -= 64 - bm; bm++; }
    int bn = bm + rem;

    {
        const uint2* gA = (const uint2*)(g_fh + bm * 128 * DD);
        const uint2* gB = (const uint2*)(g_fh + bn * 128 * DD);
#pragma unroll
        for (int it = 0; it < 8; it++) {
            int i = tid + it * 256;
            int r = i >> 4, c4 = i & 15;
            int so = (r * ADJ_AS + c4 * 4) >> 2;
            ((uint2*)sA)[so] = gA[i];
            ((uint2*)sB)[so] = gB[i];
        }
    }
    __syncthreads();

    int wid = tid >> 5, lane = tid & 31;
    int g = lane >> 2, t = lane & 3;
    int f = lane >> 3, rr = lane & 7;
    float* obase = out + OUT_ADJ;

    uint32_t aBase = smem_cast(sA + (wid * 16 + (f & 1) * 8 + rr) * ADJ_AS + (f >> 1) * 8);

#pragma unroll
    for (int h = 0; h < 2; h++) {
        float acc[8][4];
#pragma unroll
        for (int nf = 0; nf < 8; nf++)
#pragma unroll
            for (int i = 0; i < 4; i++) acc[nf][i] = 0.f;

        uint32_t bBase[4];
#pragma unroll
        for (int j = 0; j < 4; j++)
            bBase[j] = smem_cast(sB + (h * 64 + (2 * j + (f >> 1)) * 8 + rr) * ADJ_AS
                                 + (f & 1) * 8);

#pragma unroll
        for (int ks = 0; ks < 4; ks++) {
            uint32_t av[4];
            LDSM_X4(av[0], av[1], av[2], av[3], aBase + ks * 32);
#pragma unroll
            for (int j = 0; j < 4; j++) {
                uint32_t b0, b1, b2, b3;
                LDSM_X4(b0, b1, b2, b3, bBase[j] + ks * 32);
                uint32_t bb0[2] = {b0, b1};
                uint32_t bb1[2] = {b2, b3};
                mma16816h(acc[2 * j],     av, bb0);
                mma16816h(acc[2 * j + 1], av, bb1);
            }
        }

        __syncthreads();
        int r0 = wid * 16 + g;
#pragma unroll
        for (int nf = 0; nf < 8; nf++) {
            int c0 = nf * 8 + t * 2;
            float2 v0 = make_float2(fast_sigmoid(acc[nf][0]), fast_sigmoid(acc[nf][1]));
            float2 v1 = make_float2(fast_sigmoid(acc[nf][2]), fast_sigmoid(acc[nf][3]));
            *(float2*)&stage[r0 * STG_W + c0]       = v0;
            *(float2*)&stage[(r0 + 8) * STG_W + c0] = v1;
        }
        __syncthreads();

        {
            int ob = (bm * 128 + wid * 16) * NN + bn * 128 + h * 64;
#pragma unroll 4
            for (int ii = 0; ii < 16; ii++) {
                int lr = wid * 16 + ii;
                float2 v = *(const float2*)&stage[lr * STG_W + lane * 2];
                *(float2*)&obase[ob + ii * NN + lane * 2] = v;
            }
        }

        if (bm != bn) {
            int ob = (bn * 128 + h * 64 + wid * 8) * NN + bm * 128;
#pragma unroll
            for (int jj = 0; jj < 8; jj++) {
                int j = wid * 8 + jj;
#pragma unroll
                for (int p = 0; p < 4; p++) {
                    float v = stage[(p * 32 + lane) * STG_W + j];
                    obase[ob + jj * NN + p * 32 + lane] = v;
                }
            }
        }
    }
}

// ============================================================
// host launcher — single stream (R13 baseline re-verification)
// ============================================================
extern "C" void kernel_launch(void* const* d_in, const int* in_sizes, int n_in,
                              void* d_out, int out_size) {
    const float* feat = (const float*)d_in[0];
    const int*   esrc = (const int*)d_in[1];
    const int*   edst = (const int*)d_in[2];
    const float* ew   = (const float*)d_in[3];
    const float* aw   = (const float*)d_in[4];
    const int*   neg1 = (const int*)d_in[5];
    const int*   neg2 = (const int*)d_in[6];
    const int*   aidx = (const int*)d_in[7];
    const int*   nidx = (const int*)d_in[8];
    const float* alap = (const float*)d_in[9];
    const float* nlap = (const float*)d_in[10];
    const float* W1 = (const float*)d_in[11];
    const float* b1 = (const float*)d_in[12];
    const float* W2 = (const float*)d_in[13];
    const float* b2 = (const float*)d_in[14];
    const float* Wq = (const float*)d_in[15];
    const float* bq = (const float*)d_in[16];
    const float* Ws = (const float*)d_in[17];
    const float* bs = (const float*)d_in[18];
    const float* B1 = (const float*)d_in[19];
    const float* bd1 = (const float*)d_in[20];
    const float* B2 = (const float*)d_in[21];
    const float* bd2 = (const float*)d_in[22];
    const float* a1 = (const float*)d_in[23];
    const float* a2 = (const float*)d_in[24];
    const float* aq = (const float*)d_in[25];
    float* out = (float*)d_out;

    cudaFuncSetAttribute(k_adj, cudaFuncAttributeMaxDynamicSharedMemorySize, ADJ_SMEM);

    // CSR build (g_cnt arrives zeroed: static init on call 1, k_scan re-zeroes after)
    k_hist<<<EE / 4 / 256, 256>>>(edst);
    k_scan<<<1, 1024>>>(out);
    k_scatter<<<EE / 4 / 256, 256>>>(esrc, edst, ew, aw);

    // GCN layer 1
    k_gemm64<<<NN / 64, 256>>>(feat, -1, W1, /*h1*/0);
    k_agg<<<NN * 32 / 256, 256>>>(/*h1*/0, b1, a1, /*v1*/1, /*fused*/1);

    // GCN layer 2
    k_gemm64<<<NN / 64, 256>>>(nullptr, /*v1*/1, W2, /*h2*/2);
    k_agg<<<NN * 32 / 256, 256>>>(/*h2*/2, b2, a2, /*v2*/3, /*fused*/0);

    // fused: nv + score + fp16 + c1 + c2
    k_nvfuse<<<NN / 64, 256>>>(Wq, bq, aq, B1, B2, Ws, bs);

    // discriminators (dual)
    k_disc<<<dim3((NN + 255) / 256, 2), 256>>>(feat, neg1, neg2, bd1, bd2, out);

    // subgraph losses
    k_subg<<<SS, KK>>>(aidx, nidx, alap, nlap, out);

    // adjacency rebuild: 2080 upper-triangle tiles
    k_adj<<<2080, 256, ADJ_SMEM>>>(out);
}

// round 17
// speedup vs baseline: 1.4800x; 1.4800x over previous
#include <cuda_runtime.h>
#include <cuda_fp16.h>
#include <cuda_bf16.h>
#include <cstdint>

#define NN   8192
#define EE   262144
#define DD   64
#define SS   128
#define KK   128
#define NEGK 4

// ---- output layout (tuple flattened in order) ----
#define OUT_ADJ 4LL
#define OUT_P1  (4LL + (long long)NN * NN)
#define OUT_N1  (OUT_P1 + NN)
#define OUT_P2  (OUT_N1 + 4LL * NN)
#define OUT_N2  (OUT_P2 + NN)

// ---- device scratch (no allocation allowed) ----
__device__ float g_h1[NN * DD];
__device__ float g_v1[NN * DD];
__device__ float g_h2[NN * DD];
__device__ float g_v2[NN * DD];
__device__ float g_nbr[NN * DD];
__device__ float g_c1[NN * DD];
__device__ float g_c2[NN * DD];
__device__ float g_score[NN];
__device__ __half g_fh[NN * DD];
__device__ int   g_cnt[NN];      // zero-initialized; k_scan re-zeroes after use
__device__ int   g_rptr[NN + 1];
__device__ int   g_cur[NN];
__device__ uint4 g_edge[EE];     // packed (src, w_bits, aw_bits, 0)

__device__ __forceinline__ float* selBuf(int s) {
    switch (s) {
        case 0: return g_h1;
        case 1: return g_v1;
        case 2: return g_h2;
        case 3: return g_v2;
        case 5: return g_c1;
        case 6: return g_c2;
    }
    return nullptr;
}

// 1-MUFU sigmoid: sigmoid(x) = 0.5*tanh(0.5x) + 0.5
__device__ __forceinline__ float fast_sigmoid(float x) {
    float t;
    asm("tanh.approx.f32 %0, %1;" : "=f"(t) : "f"(0.5f * x));
    return fmaf(0.5f, t, 0.5f);
}

__device__ __forceinline__ uint32_t smem_cast(const void* p) {
    uint32_t a;
    asm("{ .reg .u64 t; cvta.to.shared.u64 t, %1; cvt.u32.u64 %0, t; }"
        : "=r"(a) : "l"(p));
    return a;
}

#define LDSM_X4(r0, r1, r2, r3, addr) \
    asm volatile("ldmatrix.sync.aligned.m8n8.x4.shared.b16 {%0,%1,%2,%3}, [%4];" \
                 : "=r"(r0), "=r"(r1), "=r"(r2), "=r"(r3) : "r"(addr))

// ============================================================
// 1. CSR build: histogram (x4) -> scan (self-cleaning) -> scatter
// ============================================================
__global__ void k_hist(const int* __restrict__ edst) {
    int e4 = blockIdx.x * blockDim.x + threadIdx.x;
    int4 d = ((const int4*)edst)[e4];
    atomicAdd(&g_cnt[d.x], 1);
    atomicAdd(&g_cnt[d.y], 1);
    atomicAdd(&g_cnt[d.z], 1);
    atomicAdd(&g_cnt[d.w], 1);
}

__global__ void k_scan(float* __restrict__ out) {
    __shared__ int partial[1024];
    int t = threadIdx.x;
    int base = t * 8;
    int loc[8];
    int s = 0;
#pragma unroll
    for (int i = 0; i < 8; i++) { loc[i] = s; s += g_cnt[base + i]; }
#pragma unroll
    for (int i = 0; i < 8; i++) g_cnt[base + i] = 0;   // re-zero for next call
    partial[t] = s;
    __syncthreads();
    for (int off = 1; off < 1024; off <<= 1) {
        int v = 0;
        if (t >= off) v = partial[t - off];
        __syncthreads();
        if (t >= off) partial[t] += v;
        __syncthreads();
    }
    int excl = (t == 0) ? 0 : partial[t - 1];
#pragma unroll
    for (int i = 0; i < 8; i++) {
        int v = excl + loc[i];
        g_rptr[base + i] = v;
        g_cur[base + i]  = v;
    }
    if (t == 1023) g_rptr[NN] = partial[1023];
    if (t < 4) out[t] = 0.f;                           // zero scalar outputs
}

__global__ void k_scatter(const int* __restrict__ esrc, const int* __restrict__ edst,
                          const float* __restrict__ ew, const float* __restrict__ aw) {
    int e4 = blockIdx.x * blockDim.x + threadIdx.x;
    int4   s = ((const int4*)esrc)[e4];
    int4   d = ((const int4*)edst)[e4];
    float4 w = ((const float4*)ew)[e4];
    float4 a = ((const float4*)aw)[e4];
    int p0 = atomicAdd(&g_cur[d.x], 1);
    int p1 = atomicAdd(&g_cur[d.y], 1);
    int p2 = atomicAdd(&g_cur[d.z], 1);
    int p3 = atomicAdd(&g_cur[d.w], 1);
    g_edge[p0] = make_uint4(s.x, __float_as_uint(w.x), __float_as_uint(a.x), 0);
    g_edge[p1] = make_uint4(s.y, __float_as_uint(w.y), __float_as_uint(a.y), 0);
    g_edge[p2] = make_uint4(s.z, __float_as_uint(w.z), __float_as_uint(a.z), 0);
    g_edge[p3] = make_uint4(s.w, __float_as_uint(w.w), __float_as_uint(a.w), 0);
}

// ============================================================
// 2. dense [N,64]x[64,64] GEMM — 32 rows/block (grid 256)
// ============================================================
__global__ void __launch_bounds__(256) k_gemm64(
    const float* __restrict__ Xext, int xsel,
    const float* __restrict__ W, int ysel)
{
    __shared__ float Xs[32][68];
    __shared__ float Ws[64][68];
    const float* X = Xext ? Xext : selBuf(xsel);
    float* Y = selBuf(ysel);
    int tid = threadIdx.x;
    int rowBase = blockIdx.x * 32;

    for (int i = tid; i < 4096; i += 256)
        Ws[i >> 6][i & 63] = W[i];
    for (int i = tid; i < 2048; i += 256) {
        int r = i >> 6, c = i & 63;
        Xs[r][c] = X[(rowBase + r) * 64 + c];
    }
    __syncthreads();

    int rg = tid >> 3;           // 0..31
    int cg = (tid & 7) * 8;      // 0..56
    float acc[8];
#pragma unroll
    for (int i = 0; i < 8; i++) acc[i] = 0.f;

#pragma unroll 16
    for (int k = 0; k < 64; k++) {
        float x = Xs[rg][k];
#pragma unroll
        for (int q = 0; q < 2; q++) {
            float4 w = *(const float4*)&Ws[k][cg + q * 4];
            acc[q * 4 + 0] += x * w.x;
            acc[q * 4 + 1] += x * w.y;
            acc[q * 4 + 2] += x * w.z;
            acc[q * 4 + 3] += x * w.w;
        }
    }
#pragma unroll
    for (int q = 0; q < 2; q++) {
        float4 v;
        v.x = acc[q * 4 + 0]; v.y = acc[q * 4 + 1];
        v.z = acc[q * 4 + 2]; v.w = acc[q * 4 + 3];
        *(float4*)&Y[(rowBase + rg) * 64 + cg + q * 4] = v;
    }
}

// ============================================================
// 2b. fused tail (32 rows/block): nv = prelu(v2@Wq+bq); score;
//     fp16; c1 = nv@B1^T; c2 = nv@B2
// ============================================================
__global__ void __launch_bounds__(256) k_nvfuse(
    const float* __restrict__ Wq, const float* __restrict__ bq,
    const float* __restrict__ aq,
    const float* __restrict__ B1, const float* __restrict__ B2,
    const float* __restrict__ Wsc, const float* __restrict__ bsc)
{
    __shared__ float Xs[32][68];
    __shared__ float Wsm[64][68];
    int tid = threadIdx.x;
    int rowBase = blockIdx.x * 32;
    int rg = tid >> 3;           // 0..31
    int cg = (tid & 7) * 8;      // 0..56

    for (int i = tid; i < 4096; i += 256)
        Wsm[i >> 6][i & 63] = Wq[i];
    for (int i = tid; i < 2048; i += 256) {
        int r = i >> 6, c = i & 63;
        Xs[r][c] = g_v2[(rowBase + r) * 64 + c];
    }
    __syncthreads();

    // nv = prelu(v2 @ Wq + bq)
    float nv[8];
#pragma unroll
    for (int i = 0; i < 8; i++) nv[i] = 0.f;
#pragma unroll 16
    for (int k = 0; k < 64; k++) {
        float x = Xs[rg][k];
#pragma unroll
        for (int q = 0; q < 2; q++) {
            float4 w = *(const float4*)&Wsm[k][cg + q * 4];
            nv[q * 4 + 0] += x * w.x;
            nv[q * 4 + 1] += x * w.y;
            nv[q * 4 + 2] += x * w.z;
            nv[q * 4 + 3] += x * w.w;
        }
    }
    float sl = *aq;
#pragma unroll
    for (int q = 0; q < 2; q++) {
        float4 b = *(const float4*)&bq[cg + q * 4];
        float* a = &nv[q * 4];
        a[0] += b.x; a[1] += b.y; a[2] += b.z; a[3] += b.w;
        a[0] = a[0] >= 0.f ? a[0] : sl * a[0];
        a[1] = a[1] >= 0.f ? a[1] : sl * a[1];
        a[2] = a[2] >= 0.f ? a[2] : sl * a[2];
        a[3] = a[3] >= 0.f ? a[3] : sl * a[3];
    }

    // score + fp16 convert
    {
        float p = 0.f;
#pragma unroll
        for (int q = 0; q < 2; q++) {
            float4 w = *(const float4*)&Wsc[cg + q * 4];
            p += nv[q * 4 + 0] * w.x + nv[q * 4 + 1] * w.y
               + nv[q * 4 + 2] * w.z + nv[q * 4 + 3] * w.w;
        }
        p += __shfl_down_sync(0xffffffffu, p, 1, 8);
        p += __shfl_down_sync(0xffffffffu, p, 2, 8);
        p += __shfl_down_sync(0xffffffffu, p, 4, 8);
        __half2* hp = (__half2*)(g_fh + (rowBase + rg) * DD + cg);
#pragma unroll
        for (int q = 0; q < 2; q++) {
            hp[q * 2 + 0] = __floats2half2_rn(nv[q * 4 + 0], nv[q * 4 + 1]);
            hp[q * 2 + 1] = __floats2half2_rn(nv[q * 4 + 2], nv[q * 4 + 3]);
        }
        if ((tid & 7) == 0) g_score[rowBase + rg] = fast_sigmoid(p + bsc[0]);
    }

    // stage nv into Xs; load B1^T into Wsm
    __syncthreads();
#pragma unroll
    for (int j = 0; j < 8; j++) Xs[rg][cg + j] = nv[j];
    for (int i = tid; i < 4096; i += 256)
        Wsm[i >> 6][i & 63] = B1[(i & 63) * 64 + (i >> 6)];   // transpose
    __syncthreads();

    // c1 = nv @ B1^T
    float acc[8];
#pragma unroll
    for (int i = 0; i < 8; i++) acc[i] = 0.f;
#pragma unroll 16
    for (int k = 0; k < 64; k++) {
        float x = Xs[rg][k];
#pragma unroll
        for (int q = 0; q < 2; q++) {
            float4 w = *(const float4*)&Wsm[k][cg + q * 4];
            acc[q * 4 + 0] += x * w.x;
            acc[q * 4 + 1] += x * w.y;
            acc[q * 4 + 2] += x * w.z;
            acc[q * 4 + 3] += x * w.w;
        }
    }
#pragma unroll
    for (int q = 0; q < 2; q++) {
        float4 v;
        v.x = acc[q * 4 + 0]; v.y = acc[q * 4 + 1];
        v.z = acc[q * 4 + 2]; v.w = acc[q * 4 + 3];
        *(float4*)&g_c1[(rowBase + rg) * 64 + cg + q * 4] = v;
    }

    // c2 = nv @ B2
    __syncthreads();
    for (int i = tid; i < 4096; i += 256)
        Wsm[i >> 6][i & 63] = B2[i];
    __syncthreads();
#pragma unroll
    for (int i = 0; i < 8; i++) acc[i] = 0.f;
#pragma unroll 16
    for (int k = 0; k < 64; k++) {
        float x = Xs[rg][k];
#pragma unroll
        for (int q = 0; q < 2; q++) {
            float4 w = *(const float4*)&Wsm[k][cg + q * 4];
            acc[q * 4 + 0] += x * w.x;
            acc[q * 4 + 1] += x * w.y;
            acc[q * 4 + 2] += x * w.z;
            acc[q * 4 + 3] += x * w.w;
        }
    }
#pragma unroll
    for (int q = 0; q < 2; q++) {
        float4 v;
        v.x = acc[q * 4 + 0]; v.y = acc[q * 4 + 1];
        v.z = acc[q * 4 + 2]; v.w = acc[q * 4 + 3];
        *(float4*)&g_c2[(rowBase + rg) * 64 + cg + q * 4] = v;
    }
}

// ============================================================
// 3. CSR aggregation, warp per node, optional fused avg-agg
// ============================================================
__global__ void __launch_bounds__(256) k_agg(
    int hsel, const float* __restrict__ bias, const float* __restrict__ slope,
    int vsel, int fused)
{
    int widx = (blockIdx.x * blockDim.x + threadIdx.x) >> 5;
    int lane = threadIdx.x & 31;
    if (widx >= NN) return;
    const float* h = selBuf(hsel);
    float* v = selBuf(vsel);
    int beg = g_rptr[widx], end = g_rptr[widx + 1];
    float ax = 0.f, ay = 0.f, bx = 0.f, by = 0.f;
#pragma unroll 4
    for (int j = beg; j < end; j++) {
        uint4 e = g_edge[j];
        float w = __uint_as_float(e.y);
        float2 hv = *(const float2*)(h + e.x * DD + lane * 2);
        ax += w * hv.x; ay += w * hv.y;
        if (fused) {
            float w2 = __uint_as_float(e.z);
            bx += w2 * hv.x; by += w2 * hv.y;
        }
    }
    float sl = *slope;
    float2 bb = *(const float2*)(bias + lane * 2);
    float vx = ax + bb.x; vx = vx >= 0.f ? vx : sl * vx;
    float vy = ay + bb.y; vy = vy >= 0.f ? vy : sl * vy;
    *(float2*)(v + widx * DD + lane * 2) = make_float2(vx, vy);
    if (fused)
        *(float2*)(g_nbr + widx * DD + lane * 2) = make_float2(bx, by);
}

// ============================================================
// 5. discriminators (merged: blockIdx.y 0 -> disc1, 1 -> disc2)
// ============================================================
__global__ void k_disc(const float* __restrict__ feat,
                       const int* __restrict__ neg1, const int* __restrict__ neg2,
                       const float* __restrict__ bd1, const float* __restrict__ bd2,
                       float* __restrict__ out) {
    int n = blockIdx.x * blockDim.x + threadIdx.x;
    if (n >= NN) return;
    if (blockIdx.y == 0) {
        float4 c[16];
        const float4* cr = (const float4*)(g_c1 + n * DD);
#pragma unroll
        for (int q = 0; q < 16; q++) c[q] = cr[q];
        float b = bd1[0];
        {
            const float4* f = (const float4*)(feat + n * DD);
            float a = 0.f;
#pragma unroll
            for (int q = 0; q < 16; q++) {
                float4 x = f[q];
                a += x.x * c[q].x + x.y * c[q].y + x.z * c[q].z + x.w * c[q].w;
            }
            out[OUT_P1 + n] = a + b;
        }
#pragma unroll
        for (int k = 0; k < NEGK; k++) {
            int m = neg1[k * NN + n];
            const float4* f = (const float4*)(feat + m * DD);
            float a = 0.f;
#pragma unroll
            for (int q = 0; q < 16; q++) {
                float4 x = f[q];
                a += x.x * c[q].x + x.y * c[q].y + x.z * c[q].z + x.w * c[q].w;
            }
            out[OUT_N1 + (long long)k * NN + n] = a + b;
        }
    } else {
        float4 r[16];
        const float4* nr = (const float4*)(g_nbr + n * DD);
#pragma unroll
        for (int q = 0; q < 16; q++) r[q] = nr[q];
        float b = bd2[0];
        {
            const float4* f = (const float4*)(g_c2 + n * DD);
            float a = 0.f;
#pragma unroll
            for (int q = 0; q < 16; q++) {
                float4 x = f[q];
                a += x.x * r[q].x + x.y * r[q].y + x.z * r[q].z + x.w * r[q].w;
            }
            out[OUT_P2 + n] = a + b;
        }
#pragma unroll
        for (int k = 0; k < NEGK; k++) {
            int m = neg2[k * NN + n];
            const float4* f = (const float4*)(g_c2 + m * DD);
            float a = 0.f;
#pragma unroll
            for (int q = 0; q < 16; q++) {
                float4 x = f[q];
                a += x.x * r[q].x + x.y * r[q].y + x.z * r[q].z + x.w * r[q].w;
            }
            out[OUT_N2 + (long long)k * NN + n] = a + b;
        }
    }
}

// ============================================================
// 6. subgraph losses (no sort needed: max / max-below-mean)
// ============================================================
__device__ __forceinline__ float warpRed(float v) {
#pragma unroll
    for (int o = 16; o; o >>= 1) v += __shfl_xor_sync(0xffffffffu, v, o);
    return v;
}
__device__ __forceinline__ float warpMax(float v) {
#pragma unroll
    for (int o = 16; o; o >>= 1) v = fmaxf(v, __shfl_xor_sync(0xffffffffu, v, o));
    return v;
}

__global__ void k_subg(const int* __restrict__ aidx, const int* __restrict__ nidx,
                       const float* __restrict__ alap, const float* __restrict__ nlap,
                       float* __restrict__ out) {
    int s = blockIdx.x, k = threadIdx.x;
    __shared__ float As[KK], Nss[KK];
    __shared__ float w4[16];
    float sa = g_score[aidx[s * KK + k]];
    float sn = g_score[nidx[s * KK + k]];
    As[k] = sa; Nss[k] = sn;
    __syncthreads();

    const float* la = alap + (size_t)s * KK * KK + k * KK;
    const float* ln = nlap + (size_t)s * KK * KK + k * KK;
    float ta = 0.f, tn = 0.f;
#pragma unroll 8
    for (int j = 0; j < KK; j++) { ta += la[j] * As[j]; tn += ln[j] * Nss[j]; }
    float homk = sa * ta + sn * tn;

    int w = k >> 5, l = k & 31;
    float r0 = warpRed(homk);
    float r1 = warpRed(sa);
    float r2 = warpMax(sa);
    float r3 = warpMax(sn);
    if (l == 0) { w4[0 + w] = r0; w4[4 + w] = r1; w4[8 + w] = r2; w4[12 + w] = r3; }
    __syncthreads();
    float hom_s = w4[0] + w4[1] + w4[2] + w4[3];
    float sum_a = w4[4] + w4[5] + w4[6] + w4[7];
    float max_a = fmaxf(fmaxf(w4[8], w4[9]), fmaxf(w4[10], w4[11]));
    float max_n = fmaxf(fmaxf(w4[12], w4[13]), fmaxf(w4[14], w4[15]));
    float mean = sum_a * (1.f / KK);
    float below = (sa < mean) ? sa : -1e30f;
    float bw = warpMax(below);
    __syncthreads();
    if (l == 0) w4[w] = bw;
    __syncthreads();
    if (k == 0) {
        float bm = fmaxf(fmaxf(w4[0], w4[1]), fmaxf(w4[2], w4[3]));
        float a_at = (bm <= -1e29f) ? max_a : bm;
        atomicAdd(out + 0, fmaxf(0.f, 1.f - max_a + max_n) * (1.f / SS));
        atomicAdd(out + 1, fmaxf(0.f, 1.f - max_a + a_at) * (1.f / SS));
        atomicAdd(out + 2, sum_a * (1.f / SS));
        atomicAdd(out + 3, hom_s * (1.f / (2.f * SS)));
    }
}

// ============================================================
// 7. adj_rebuilt = sigmoid(nv @ nv^T): fp16 HMMA + LDSM loads,
//    upper-triangle tiles, 2 column-halves, staged epilogue.
// ============================================================
__device__ __forceinline__ void mma16816h(float* c, const uint32_t* a, const uint32_t* b) {
    asm volatile(
        "mma.sync.aligned.m16n8k16.row.col.f32.f16.f16.f32 "
        "{%0,%1,%2,%3}, {%4,%5,%6,%7}, {%8,%9}, {%0,%1,%2,%3};\n"
        : "+f"(c[0]), "+f"(c[1]), "+f"(c[2]), "+f"(c[3])
        : "r"(a[0]), "r"(a[1]), "r"(a[2]), "r"(a[3]), "r"(b[0]), "r"(b[1]));
}

#define ADJ_AS   72     // 144B row stride: conflict-free LDSM
#define STG_W    66     // even stride: 8B-aligned float2 accesses
#define ADJ_TILES_SMEM (128 * ADJ_AS * 2 * 2)          // A + B = 36864
#define ADJ_SMEM (ADJ_TILES_SMEM + 128 * STG_W * 4)    // + stage = 70656

__global__ void __launch_bounds__(256, 3) k_adj(float* __restrict__ out) {
    extern __shared__ char dsm[];
    __half* sA = (__half*)dsm;
    __half* sB = (__half*)(dsm + 128 * ADJ_AS * 2);
    float*  stage = (float*)(dsm + ADJ_TILES_SMEM);

    int tid = threadIdx.x;

    // tile id -> (bm, bn) upper triangle, bm <= bn
    int rem = blockIdx.x, bm = 0;
    while (rem >= 64 - bm) { rem -= 64 - bm; bm++; }
    int bn = bm + rem;

    {
        const uint2* gA = (const uint2*)(g_fh + bm * 128 * DD);
        const uint2* gB = (const uint2*)(g_fh + bn * 128 * DD);
#pragma unroll
        for (int it = 0; it < 8; it++) {
            int i = tid + it * 256;
            int r = i >> 4, c4 = i & 15;
            int so = (r * ADJ_AS + c4 * 4) >> 2;
            ((uint2*)sA)[so] = gA[i];
            ((uint2*)sB)[so] = gB[i];
        }
    }
    __syncthreads();

    int wid = tid >> 5, lane = tid & 31;
    int g = lane >> 2, t = lane & 3;
    int f = lane >> 3, rr = lane & 7;
    float* obase = out + OUT_ADJ;

    uint32_t aBase = smem_cast(sA + (wid * 16 + (f & 1) * 8 + rr) * ADJ_AS + (f >> 1) * 8);

#pragma unroll
    for (int h = 0; h < 2; h++) {
        float acc[8][4];
#pragma unroll
        for (int nf = 0; nf < 8; nf++)
#pragma unroll
            for (int i = 0; i < 4; i++) acc[nf][i] = 0.f;

        uint32_t bBase[4];
#pragma unroll
        for (int j = 0; j < 4; j++)
            bBase[j] = smem_cast(sB + (h * 64 + (2 * j + (f >> 1)) * 8 + rr) * ADJ_AS
                                 + (f & 1) * 8);

#pragma unroll
        for (int ks = 0; ks < 4; ks++) {
            uint32_t av[4];
            LDSM_X4(av[0], av[1], av[2], av[3], aBase + ks * 32);
#pragma unroll
            for (int j = 0; j < 4; j++) {
                uint32_t b0, b1, b2, b3;
                LDSM_X4(b0, b1, b2, b3, bBase[j] + ks * 32);
                uint32_t bb0[2] = {b0, b1};
                uint32_t bb1[2] = {b2, b3};
                mma16816h(acc[2 * j],     av, bb0);
                mma16816h(acc[2 * j + 1], av, bb1);
            }
        }

        __syncthreads();
        int r0 = wid * 16 + g;
#pragma unroll
        for (int nf = 0; nf < 8; nf++) {
            int c0 = nf * 8 + t * 2;
            float2 v0 = make_float2(fast_sigmoid(acc[nf][0]), fast_sigmoid(acc[nf][1]));
            float2 v1 = make_float2(fast_sigmoid(acc[nf][2]), fast_sigmoid(acc[nf][3]));
            *(float2*)&stage[r0 * STG_W + c0]       = v0;
            *(float2*)&stage[(r0 + 8) * STG_W + c0] = v1;
        }
        __syncthreads();

        {
            int ob = (bm * 128 + wid * 16) * NN + bn * 128 + h * 64;
#pragma unroll 4
            for (int ii = 0; ii < 16; ii++) {
                int lr = wid * 16 + ii;
                float2 v = *(const float2*)&stage[lr * STG_W + lane * 2];
                *(float2*)&obase[ob + ii * NN + lane * 2] = v;
            }
        }

        if (bm != bn) {
            int ob = (bn * 128 + h * 64 + wid * 8) * NN + bm * 128;
#pragma unroll
            for (int jj = 0; jj < 8; jj++) {
                int j = wid * 8 + jj;
#pragma unroll
                for (int p = 0; p < 4; p++) {
                    float v = stage[(p * 32 + lane) * STG_W + j];
                    obase[ob + jj * NN + p * 32 + lane] = v;
                }
            }
        }
    }
}

// ============================================================
// host launcher — single stream
// ============================================================
extern "C" void kernel_launch(void* const* d_in, const int* in_sizes, int n_in,
                              void* d_out, int out_size) {
    const float* feat = (const float*)d_in[0];
    const int*   esrc = (const int*)d_in[1];
    const int*   edst = (const int*)d_in[2];
    const float* ew   = (const float*)d_in[3];
    const float* aw   = (const float*)d_in[4];
    const int*   neg1 = (const int*)d_in[5];
    const int*   neg2 = (const int*)d_in[6];
    const int*   aidx = (const int*)d_in[7];
    const int*   nidx = (const int*)d_in[8];
    const float* alap = (const float*)d_in[9];
    const float* nlap = (const float*)d_in[10];
    const float* W1 = (const float*)d_in[11];
    const float* b1 = (const float*)d_in[12];
    const float* W2 = (const float*)d_in[13];
    const float* b2 = (const float*)d_in[14];
    const float* Wq = (const float*)d_in[15];
    const float* bq = (const float*)d_in[16];
    const float* Ws = (const float*)d_in[17];
    const float* bs = (const float*)d_in[18];
    const float* B1 = (const float*)d_in[19];
    const float* bd1 = (const float*)d_in[20];
    const float* B2 = (const float*)d_in[21];
    const float* bd2 = (const float*)d_in[22];
    const float* a1 = (const float*)d_in[23];
    const float* a2 = (const float*)d_in[24];
    const float* aq = (const float*)d_in[25];
    float* out = (float*)d_out;

    cudaFuncSetAttribute(k_adj, cudaFuncAttributeMaxDynamicSharedMemorySize, ADJ_SMEM);

    // CSR build (g_cnt arrives zeroed: static init on call 1, k_scan re-zeroes after)
    k_hist<<<EE / 4 / 256, 256>>>(edst);
    k_scan<<<1, 1024>>>(out);
    k_scatter<<<EE / 4 / 256, 256>>>(esrc, edst, ew, aw);

    // GCN layer 1
    k_gemm64<<<NN / 32, 256>>>(feat, -1, W1, /*h1*/0);
    k_agg<<<NN * 32 / 256, 256>>>(/*h1*/0, b1, a1, /*v1*/1, /*fused*/1);

    // GCN layer 2
    k_gemm64<<<NN / 32, 256>>>(nullptr, /*v1*/1, W2, /*h2*/2);
    k_agg<<<NN * 32 / 256, 256>>>(/*h2*/2, b2, a2, /*v2*/3, /*fused*/0);

    // fused: nv + score + fp16 + c1 + c2
    k_nvfuse<<<NN / 32, 256>>>(Wq, bq, aq, B1, B2, Ws, bs);

    // discriminators (dual)
    k_disc<<<dim3((NN + 255) / 256, 2), 256>>>(feat, neg1, neg2, bd1, bd2, out);

    // subgraph losses
    k_subg<<<SS, KK>>>(aidx, nidx, alap, nlap, out);

    // adjacency rebuild: 2080 upper-triangle tiles
    k_adj<<<2080, 256, ADJ_SMEM>>>(out);
}